// round 4
// baseline (speedup 1.0000x reference)
#include <cuda_runtime.h>
#include <cuda_bf16.h>

// SMorph layer: y = softdilate(x,k1) + softerode(x,k2) + bias
// Factorized via exp(p+k)=exp(p)exp(k):
//   den = conv((e,em),(A1,A2))  num = conv((pe,pem),(A1,A2)) + conv((e,em),(B1,B2))
//   out = num.x/den.x + num.y/den.y + bias   [f32x2 lanes: dilate|erode]
//
// Round 4: retile 63x7 -> grid 288 = one ~97% wave at 2 CTA/SM, no tail,
// no border clamps (63*2 and 7*18 tile 126 exactly; halo stays inside 128).
// Per thread: 7 vertical pixels x 4 filters; per (c,kw) 9 map rows loaded
// once, reused over 3 kh x 7 px.

#define BATCH 8
#define CIN   3
#define HIN   128
#define WIN   128
#define FOUT  16
#define HOUT  126
#define WOUT  126

#define TW    63           // tile width  (cols)
#define TH    7            // tile height (rows)
#define TINW  65           // TW + 2 halo
#define TINH  9            // TH + 2 halo

__device__ __forceinline__ void ffma2(unsigned long long& d,
                                      unsigned long long a,
                                      unsigned long long b)
{
    asm("fma.rn.f32x2 %0, %1, %2, %0;" : "+l"(d) : "l"(a), "l"(b));
}

__device__ __forceinline__ float2 unpack2(unsigned long long v)
{
    float2 r;
    asm("mov.b64 {%0, %1}, %2;" : "=f"(r.x), "=f"(r.y) : "l"(v));
    return r;
}

__global__ __launch_bounds__(256, 2)
void smorph_kernel(const float* __restrict__ x,
                   const float* __restrict__ k1,
                   const float* __restrict__ k2,
                   const float* __restrict__ bias,
                   float* __restrict__ out)
{
    __shared__ float4 sMap[CIN][TINH][TINW];   // (e,em,pe,pem) 3*9*65*16 = 28080 B
    __shared__ float4 sW[27][FOUT];            // (A1,A2,B1,B2)          6912 B
    __shared__ float  sBias[FOUT];

    const int tid  = threadIdx.x;
    const int fc   = tid >> 6;                 // filter chunk 0..3
    const int col  = tid & 63;                 // 0..63 (63 = idle lane)
    const int colc = min(col, TW - 1);         // clamp idle lane's loads in-range
    const int bx   = blockIdx.x, by = blockIdx.y, b = blockIdx.z;
    const int gx0  = bx * TW,  gy0 = by * TH;

    // ---- Weight precompute: j = c*9 + kh*3 + kw ; mem idx ((kh*3+kw)*3+c)*16+f
    if (tid < FOUT) sBias[tid] = bias[tid];
    for (int i = tid; i < 27 * FOUT; i += 256) {
        int j = i >> 4, f = i & 15;
        int c = j / 9, r = j - c * 9;
        int gi = (r * 3 + c) * FOUT + f;
        float w1 = k1[gi], w2 = k2[gi];
        float a1 = __expf(w1), a2 = __expf(w2);
        sW[j][f] = make_float4(a1, a2, w1 * a1, w2 * a2);
    }

    // ---- Tile load + map precompute (always in-bounds: gy0+8<=127, gx0+64<=127)
    for (int i = tid; i < CIN * TINH * TINW; i += 256) {
        int c   = i / (TINH * TINW);
        int rem = i - c * (TINH * TINW);
        int r   = rem / TINW;
        int cc  = rem - r * TINW;
        float v  = x[((b * CIN + c) * HIN + (gy0 + r)) * WIN + (gx0 + cc)];
        float e  = __expf(v);
        float em = __expf(-v);
        sMap[c][r][cc] = make_float4(e, em, v * e, -v * em);
    }
    __syncthreads();

    // ---- Accumulators: [fi][px], packed (dilate,erode)
    unsigned long long den[4][TH], num[4][TH];
#pragma unroll
    for (int fi = 0; fi < 4; fi++)
#pragma unroll
        for (int p = 0; p < TH; p++) { den[fi][p] = 0ull; num[fi][p] = 0ull; }

#pragma unroll 1
    for (int c = 0; c < CIN; c++) {
#pragma unroll
        for (int kw = 0; kw < 3; kw++) {
            // Load the 9 map rows this (c,kw) column needs, once.
            ulonglong2 p[TINH];
#pragma unroll
            for (int rr = 0; rr < TINH; rr++)
                p[rr] = *reinterpret_cast<const ulonglong2*>(
                            &sMap[c][rr][colc + kw]);
#pragma unroll
            for (int kh = 0; kh < 3; kh++) {
                const int j = c * 9 + kh * 3 + kw;
#pragma unroll
                for (int fi = 0; fi < 4; fi++) {
                    const ulonglong2 w =
                        *reinterpret_cast<const ulonglong2*>(&sW[j][fc * 4 + fi]);
#pragma unroll
                    for (int px = 0; px < TH; px++) {
                        ffma2(den[fi][px], p[px + kh].x, w.x); // (e,em)*(A1,A2)
                        ffma2(num[fi][px], p[px + kh].y, w.x); // (pe,pem)*(A1,A2)
                        ffma2(num[fi][px], p[px + kh].x, w.y); // (e,em)*(B1,B2)
                    }
                }
            }
        }
    }

    // ---- Epilogue: 4 filters x 7 pixels (idle lane col==63 stores nothing)
    if (col < TW) {
        const int ow = gx0 + col;
#pragma unroll
        for (int fi = 0; fi < 4; fi++) {
            const int f = fc * 4 + fi;
            const float bz = sBias[f];
#pragma unroll
            for (int px = 0; px < TH; px++) {
                float2 n = unpack2(num[fi][px]);
                float2 d = unpack2(den[fi][px]);
                out[((b * FOUT + f) * HOUT + (gy0 + px)) * WOUT + ow] =
                    __fdividef(n.x, d.x) + __fdividef(n.y, d.y) + bz;
            }
        }
    }
}

extern "C" void kernel_launch(void* const* d_in, const int* in_sizes, int n_in,
                              void* d_out, int out_size)
{
    const float* x    = (const float*)d_in[0];
    const float* k1   = (const float*)d_in[1];
    const float* k2   = (const float*)d_in[2];
    const float* bias = (const float*)d_in[3];
    float* out = (float*)d_out;

    dim3 grid(WOUT / TW,    // 2
              HOUT / TH,    // 18
              BATCH);       // 8
    smorph_kernel<<<grid, 256>>>(x, k1, k2, bias, out);
}

// round 5
// speedup vs baseline: 2.6298x; 2.6298x over previous
#include <cuda_runtime.h>
#include <cuda_bf16.h>

// SMorph layer: y = softdilate(x,k1) + softerode(x,k2) + bias
// Factorized via exp(p+k)=exp(p)exp(k):
//   den = conv((e,em),(A1,A2))  num = conv((pe,pem),(A1,A2)) + conv((e,em),(B1,B2))
//   out = num.x/den.x + num.y/den.y + bias   [f32x2 lanes: dilate|erode]
//
// Round 5: 63x7 tile (grid 288 = one ~97% wave, no border clamps) with the
// filter dimension split into TWO SEQUENTIAL PASSES of 2 filters each so
// live accumulators are den[2][7]+num[2][7] = 56 regs (round 4's 4-filter
// version spilled at 112 acc regs). Each pass has its own epilogue.

#define BATCH 8
#define CIN   3
#define HIN   128
#define WIN   128
#define FOUT  16
#define HOUT  126
#define WOUT  126

#define TW    63           // tile width  (cols)
#define TH    7            // tile height (rows)
#define TINW  65           // TW + 2 halo
#define TINH  9            // TH + 2 halo

__device__ __forceinline__ void ffma2(unsigned long long& d,
                                      unsigned long long a,
                                      unsigned long long b)
{
    asm("fma.rn.f32x2 %0, %1, %2, %0;" : "+l"(d) : "l"(a), "l"(b));
}

__device__ __forceinline__ float2 unpack2(unsigned long long v)
{
    float2 r;
    asm("mov.b64 {%0, %1}, %2;" : "=f"(r.x), "=f"(r.y) : "l"(v));
    return r;
}

__global__ __launch_bounds__(256, 2)
void smorph_kernel(const float* __restrict__ x,
                   const float* __restrict__ k1,
                   const float* __restrict__ k2,
                   const float* __restrict__ bias,
                   float* __restrict__ out)
{
    __shared__ float4 sMap[CIN][TINH][TINW];   // (e,em,pe,pem) 3*9*65*16 = 28080 B
    __shared__ float4 sW[27][FOUT];            // (A1,A2,B1,B2)          6912 B
    __shared__ float  sBias[FOUT];

    const int tid  = threadIdx.x;
    const int fc   = tid >> 6;                 // filter chunk 0..3 (4 filters each)
    const int col  = tid & 63;                 // 0..63 (63 = idle lane)
    const int colc = min(col, TW - 1);         // keep idle lane's loads in-range
    const int bx   = blockIdx.x, by = blockIdx.y, b = blockIdx.z;
    const int gx0  = bx * TW,  gy0 = by * TH;

    // ---- Weight precompute: j = c*9 + kh*3 + kw ; mem idx ((kh*3+kw)*3+c)*16+f
    if (tid < FOUT) sBias[tid] = bias[tid];
    for (int i = tid; i < 27 * FOUT; i += 256) {
        int j = i >> 4, f = i & 15;
        int c = j / 9, r = j - c * 9;
        int gi = (r * 3 + c) * FOUT + f;
        float w1 = k1[gi], w2 = k2[gi];
        float a1 = __expf(w1), a2 = __expf(w2);
        sW[j][f] = make_float4(a1, a2, w1 * a1, w2 * a2);
    }

    // ---- Tile load + map precompute (always in-bounds: gy0+8<=127, gx0+64<=127)
    for (int i = tid; i < CIN * TINH * TINW; i += 256) {
        int c   = i / (TINH * TINW);
        int rem = i - c * (TINH * TINW);
        int r   = rem / TINW;
        int cc  = rem - r * TINW;
        float v  = x[((b * CIN + c) * HIN + (gy0 + r)) * WIN + (gx0 + cc)];
        float e  = __expf(v);
        float em = __expf(-v);
        sMap[c][r][cc] = make_float4(e, em, v * e, -v * em);
    }
    __syncthreads();

    const int ow = gx0 + col;

    // ---- Two sequential passes of 2 filters each (keeps acc regs at 56).
#pragma unroll 1
    for (int pass = 0; pass < 2; pass++) {
        const int f0 = fc * 4 + pass * 2;      // this pass's first filter

        unsigned long long den[2][TH], num[2][TH];
#pragma unroll
        for (int fi = 0; fi < 2; fi++)
#pragma unroll
            for (int p = 0; p < TH; p++) { den[fi][p] = 0ull; num[fi][p] = 0ull; }

#pragma unroll 1
        for (int c = 0; c < CIN; c++) {
#pragma unroll
            for (int kw = 0; kw < 3; kw++) {
                // Load the 9 map rows this (c,kw) column needs, once per pass.
                ulonglong2 p[TINH];
#pragma unroll
                for (int rr = 0; rr < TINH; rr++)
                    p[rr] = *reinterpret_cast<const ulonglong2*>(
                                &sMap[c][rr][colc + kw]);
#pragma unroll
                for (int kh = 0; kh < 3; kh++) {
                    const int j = c * 9 + kh * 3 + kw;
#pragma unroll
                    for (int fi = 0; fi < 2; fi++) {
                        const ulonglong2 w =
                            *reinterpret_cast<const ulonglong2*>(&sW[j][f0 + fi]);
#pragma unroll
                        for (int px = 0; px < TH; px++) {
                            ffma2(den[fi][px], p[px + kh].x, w.x); // (e,em)*(A1,A2)
                            ffma2(num[fi][px], p[px + kh].y, w.x); // (pe,pem)*(A1,A2)
                            ffma2(num[fi][px], p[px + kh].x, w.y); // (e,em)*(B1,B2)
                        }
                    }
                }
            }
        }

        // ---- Epilogue for this pass: 2 filters x 7 pixels
        if (col < TW) {
#pragma unroll
            for (int fi = 0; fi < 2; fi++) {
                const int f = f0 + fi;
                const float bz = sBias[f];
#pragma unroll
                for (int px = 0; px < TH; px++) {
                    float2 n = unpack2(num[fi][px]);
                    float2 d = unpack2(den[fi][px]);
                    out[((b * FOUT + f) * HOUT + (gy0 + px)) * WOUT + ow] =
                        __fdividef(n.x, d.x) + __fdividef(n.y, d.y) + bz;
                }
            }
        }
    }
}

extern "C" void kernel_launch(void* const* d_in, const int* in_sizes, int n_in,
                              void* d_out, int out_size)
{
    const float* x    = (const float*)d_in[0];
    const float* k1   = (const float*)d_in[1];
    const float* k2   = (const float*)d_in[2];
    const float* bias = (const float*)d_in[3];
    float* out = (float*)d_out;

    dim3 grid(WOUT / TW,    // 2
              HOUT / TH,    // 18
              BATCH);       // 8
    smorph_kernel<<<grid, 256>>>(x, k1, k2, bias, out);
}